// round 3
// baseline (speedup 1.0000x reference)
#include <cuda_runtime.h>
#include <math.h>

// ---------------------------------------------------------------------------
// Projection_12438225290005: tube-of-response projection, 3 axis frames.
//
// Frame mapping (image is [g0,g1,g2] row-major, idx = a*g1*g2 + b*g2 + c):
//   pz: perm (0,1,2): addr = jx*g1*g2 + jy*g2 + kz        (walk stride 1)
//   py: perm (1,0,2): addr = jy*g1*g2 + jx*g2 + kz        (walk stride 1)
//   px: perm (2,0,1): addr = jy*g1*g2 + kz*g2 + jx        (walk stride g2 -> BAD)
// For px we pre-transpose into T[a][c][b] = img[a][b][c] so
//   img[jy][kz][jx] = T[jy][jx][kz]  -> addr = jy*G^2 + jx*G + kz (stride 1).
// ---------------------------------------------------------------------------

#define G_FIXED 128

__device__ float g_imgT[G_FIXED * G_FIXED * G_FIXED];  // static scratch (no alloc)

// out[a][c][b] = in[a][b][c], G=128, tiled 32x32 transpose per a-plane.
__global__ void transpose_bc_kernel(const float* __restrict__ in) {
    __shared__ float tile[32][33];
    const int a  = blockIdx.z;
    const int b0 = blockIdx.y * 32;
    const int c0 = blockIdx.x * 32;
    const float* src = in      + (size_t)a * G_FIXED * G_FIXED;
    float*       dst = g_imgT  + (size_t)a * G_FIXED * G_FIXED;
#pragma unroll
    for (int i = threadIdx.y; i < 32; i += 8)
        tile[i][threadIdx.x] = src[(b0 + i) * G_FIXED + c0 + threadIdx.x];
    __syncthreads();
#pragma unroll
    for (int i = threadIdx.y; i < 32; i += 8)
        dst[(c0 + i) * G_FIXED + b0 + threadIdx.x] = tile[threadIdx.x][i];
}

// One block per LOR; thread t handles slices kz = t, t+128, ...
// P0/P1/P2 = image axis backing frame axis 0/1/2. TPOSE: use g_imgT strides.
template <int P0, int P1, int P2, bool TPOSE>
__global__ __launch_bounds__(128)
void tor_project_kernel(const float* __restrict__ img_in,
                        const int*   __restrict__ grid,
                        const float* __restrict__ center,
                        const float* __restrict__ size,
                        const float* __restrict__ lors,
                        float*       __restrict__ out,
                        int n_lors)
{
    const int lor = blockIdx.x;
    if (lor >= n_lors) return;

    const int g0 = grid[0], g1 = grid[1], g2 = grid[2];
    const int gs[3]   = { g0, g1, g2 };
    const int istr[3] = { g1 * g2, g2, 1 };

    const int n0 = gs[P0], n1 = gs[P1], n2 = gs[P2];

    int s0, s1, s2;
    const float* img;
    if (TPOSE) {
        s0 = G_FIXED; s1 = G_FIXED * G_FIXED; s2 = 1;
        img = g_imgT;
    } else {
        s0 = istr[P0]; s1 = istr[P1]; s2 = istr[P2];
        img = img_in;
    }

    const float sz0 = size[P0], sz1 = size[P1], sz2 = size[P2];
    const float vs0 = sz0 / (float)n0;
    const float vs1 = sz1 / (float)n1;
    const float vs2 = sz2 / (float)n2;
    const float lo0 = center[P0] - sz0 * 0.5f;
    const float lo1 = center[P1] - sz1 * 0.5f;
    const float lo2 = center[P2] - sz2 * 0.5f;

    const float* L = lors + (size_t)lor * 6;
    const float p1x = __ldg(L + 0), p1y = __ldg(L + 1), p1z = __ldg(L + 2);
    const float dx  = __ldg(L + 3) - p1x;
    const float dy  = __ldg(L + 4) - p1y;
    const float dz  = __ldg(L + 5) - p1z;
    const float len  = sqrtf(dx * dx + dy * dy + dz * dz);
    const float step = vs2 * len / fabsf(dz);
    const float inv_dz  = 1.0f / dz;
    const float inv_vs0 = 1.0f / vs0;
    const float inv_vs1 = 1.0f / vs1;

    const float KW2    = 2.8647889756541160f;   // (3*3/pi)
    const float INV_KW = 0.59081795026046127f;  // 1/sqrt(9/pi)

    float acc = 0.0f;

    for (int kz = threadIdx.x; kz < n2; kz += blockDim.x) {
        const float zc = lo2 + ((float)kz + 0.5f) * vs2;
        const float t  = (zc - p1z) * inv_dz;
        const float cx = fmaf(t, dx, p1x);
        const float cy = fmaf(t, dy, p1y);
        const float fx = (cx - lo0) * inv_vs0 - 0.5f;
        const float fy = (cy - lo1) * inv_vs1 - 0.5f;
        const int ix = (int)rintf(fx);   // round-half-to-even == jnp.round
        const int iy = (int)rintf(fy);
        const int baseK = kz * s2;

#pragma unroll
        for (int o0 = -2; o0 <= 2; ++o0) {
#pragma unroll
            for (int o1 = -2; o1 <= 2; ++o1) {
                // (+-2, +-2) corners: min dist = sqrt(1.5^2+1.5^2) = 2.12 > kw -> always 0
                if (o0 * o0 + o1 * o1 == 8) continue;
                const int jx = ix + o0;
                const int jy = iy + o1;
                const float ddx = (float)jx - fx;
                const float ddy = (float)jy - fy;
                const float d2  = ddx * ddx + ddy * ddy;
                if (d2 < KW2 && (unsigned)jx < (unsigned)n0 && (unsigned)jy < (unsigned)n1) {
                    const float w = 1.0f - sqrtf(d2) * INV_KW;
                    acc = fmaf(w, __ldg(&img[jx * s0 + jy * s1 + baseK]), acc);
                }
            }
        }
    }

    // block reduction over 128 threads (4 warps)
#pragma unroll
    for (int sft = 16; sft > 0; sft >>= 1)
        acc += __shfl_down_sync(0xFFFFFFFFu, acc, sft);

    __shared__ float wsum[4];
    const int lane = threadIdx.x & 31;
    const int wid  = threadIdx.x >> 5;
    if (lane == 0) wsum[wid] = acc;
    __syncthreads();
    if (threadIdx.x == 0) {
        float s = wsum[0] + wsum[1] + wsum[2] + wsum[3];
        out[lor] = s * step;
    }
}

extern "C" void kernel_launch(void* const* d_in, const int* in_sizes, int n_in,
                              void* d_out, int out_size)
{
    const float* image  = (const float*)d_in[0];
    const int*   grid   = (const int*)  d_in[1];
    const float* center = (const float*)d_in[2];
    const float* size   = (const float*)d_in[3];
    const float* xlors  = (const float*)d_in[4];
    const float* ylors  = (const float*)d_in[5];
    const float* zlors  = (const float*)d_in[6];
    float* out = (float*)d_out;

    const int nx = in_sizes[4] / 6;
    const int ny = in_sizes[5] / 6;
    const int nz = in_sizes[6] / 6;

    const long long nimg = in_sizes[0];
    const bool cubic128 = (nimg == (long long)G_FIXED * G_FIXED * G_FIXED);

    // px: perm (2,0,1) — walked image axis is axis 1 (stride g2); use transposed copy.
    if (cubic128) {
        dim3 tb(32, 8), tg(G_FIXED / 32, G_FIXED / 32, G_FIXED);
        transpose_bc_kernel<<<tg, tb>>>(image);
        if (nx > 0)
            tor_project_kernel<2, 0, 1, true><<<nx, 128>>>(
                image, grid, center, size, xlors, out, nx);
    } else {
        if (nx > 0)
            tor_project_kernel<2, 0, 1, false><<<nx, 128>>>(
                image, grid, center, size, xlors, out, nx);
    }
    // py: perm (1,0,2)
    if (ny > 0)
        tor_project_kernel<1, 0, 2, false><<<ny, 128>>>(
            image, grid, center, size, ylors, out + nx, ny);
    // pz: perm (0,1,2)
    if (nz > 0)
        tor_project_kernel<0, 1, 2, false><<<nz, 128>>>(
            image, grid, center, size, zlors, out + nx + ny, nz);
}

// round 6
// speedup vs baseline: 1.5764x; 1.5764x over previous
#include <cuda_runtime.h>
#include <math.h>

// ---------------------------------------------------------------------------
// Projection_12438225290005: tube-of-response projection, 3 axis frames.
//
// R5 = R3/R4 design with the REAL bug fixed: never pass a __device__ global
// (g_imgT) as a host-side kernel argument — the host shadow address is not a
// device pointer (px kernel faulted, poisoning the context; all outputs
// stayed at the harness poison -> rel_err exactly 1.0). Select g_imgT inside
// device code via a template bool, exactly like the passing R2 kernel did.
//
// Design (hot kernel is issue/ALU-bound per R2 ncu: issue 68.6%, fma+alu 62%):
//   - prep kernel precomputes per-LOR linear coefficients fx(kz)=Ax+Bx*kz,
//     fy(kz)=Ay+By*kz and step  -> no divisions / setup in hot kernel
//   - G=128 compile-time strides -> LDG with immediate offsets
//   - one-shot interior bounds check per thread (geometry: transverse coords
//     are convex combos of [-60,60] -> ix,iy in [3,124], always interior)
//   - 5 cross taps (o0^2+o1^2<=1) provably pass d2<kw^2 (max d2=2.5<2.865)
//   - (+-2,+-2) corners provably zero (min d2=4.5) -> dropped at compile time
// ---------------------------------------------------------------------------

#define G 128
#define GSQ (G * G)
#define MAX_LORS (1 << 20)

__device__ float  g_imgT[G * G * G];          // transposed image for px frame
__device__ float4 g_prm[3][MAX_LORS];         // Ax, Bx, Ay, By
__device__ float  g_stp[3][MAX_LORS];         // step

// g_imgT[a][c][b] = in[a][b][c]
__global__ void transpose_bc_kernel(const float* __restrict__ in) {
    __shared__ float tile[32][33];
    const int a  = blockIdx.z;
    const int b0 = blockIdx.y * 32;
    const int c0 = blockIdx.x * 32;
    const float* src = in     + (size_t)a * GSQ;
    float*       dst = g_imgT + (size_t)a * GSQ;
#pragma unroll
    for (int i = threadIdx.y; i < 32; i += 8)
        tile[i][threadIdx.x] = src[(b0 + i) * G + c0 + threadIdx.x];
    __syncthreads();
#pragma unroll
    for (int i = threadIdx.y; i < 32; i += 8)
        dst[(c0 + i) * G + b0 + threadIdx.x] = tile[threadIdx.x][i];
}

// One thread per LOR: fold all frame/LOR setup into linear coefficients.
// P0/P1/P2 permute grid/center/size ONLY; lors are already frame-local.
template <int P0, int P1, int P2>
__global__ void prep_kernel(const int*   __restrict__ grid,
                            const float* __restrict__ center,
                            const float* __restrict__ size,
                            const float* __restrict__ lors,
                            int n, int set)
{
    int i = blockIdx.x * blockDim.x + threadIdx.x;
    if (i >= n) return;
    const float sz0 = size[P0], sz1 = size[P1], sz2 = size[P2];
    const int   n0 = grid[P0], n1 = grid[P1], n2 = grid[P2];
    const float vs0 = sz0 / (float)n0;
    const float vs1 = sz1 / (float)n1;
    const float vs2 = sz2 / (float)n2;
    const float lo0 = center[P0] - 0.5f * sz0;
    const float lo1 = center[P1] - 0.5f * sz1;
    const float lo2 = center[P2] - 0.5f * sz2;

    const float* L = lors + (size_t)i * 6;
    const float p10 = L[0], p11 = L[1], p12 = L[2];   // frame-local coords
    const float d0  = L[3] - p10;
    const float d1  = L[4] - p11;
    const float d2c = L[5] - p12;
    const float len = sqrtf(d0 * d0 + d1 * d1 + d2c * d2c);
    const float inv_dz = 1.0f / d2c;
    // t(kz) = t0 + kz*dt, zc = lo2 + (kz+0.5)*vs2
    const float t0 = (lo2 + 0.5f * vs2 - p12) * inv_dz;
    const float dt = vs2 * inv_dz;
    const float Ax = (p10 + t0 * d0 - lo0) / vs0 - 0.5f;
    const float Bx = dt * d0 / vs0;
    const float Ay = (p11 + t0 * d1 - lo1) / vs1 - 0.5f;
    const float By = dt * d1 / vs1;
    g_prm[set][i] = make_float4(Ax, Bx, Ay, By);
    g_stp[set][i] = vs2 * len / fabsf(d2c);
}

// Hot kernel: one block per LOR, thread = slice kz (n2 == G == blockDim).
// S0/S1 compile-time strides; walked axis stride is 1 for all three frames.
// TPOSE selects the device-global transposed image (device-side only!).
template <int S0, int S1, bool TPOSE>
__global__ __launch_bounds__(128)
void tor_fast_kernel(const float* __restrict__ img_in, int set,
                     float* __restrict__ out)
{
    const float* img = TPOSE ? (const float*)g_imgT : img_in;

    const int lor = blockIdx.x;
    const float4 P = __ldg(&g_prm[set][lor]);
    const float kzf = (float)threadIdx.x;
    const float fx = fmaf(kzf, P.y, P.x);
    const float fy = fmaf(kzf, P.w, P.z);
    const int ix = __float2int_rn(fx);   // round-half-to-even == jnp.round
    const int iy = __float2int_rn(fy);

    const float KW2    = 2.8647889756541160f;   // (3*3/pi)
    const float INV_KW = 0.59081795026046127f;  // 1/sqrt(9/pi)

    const float ux = (float)ix - fx;             // in [-0.5, 0.5]
    const float uy = (float)iy - fy;
    float xs[5], ys[5];
#pragma unroll
    for (int o = 0; o < 5; ++o) {
        const float a = ux + (float)(o - 2);
        const float b = uy + (float)(o - 2);
        xs[o] = a * a;
        ys[o] = b * b;
    }

    float acc = 0.0f;
    if ((unsigned)(ix - 2) <= (unsigned)(G - 5) &&
        (unsigned)(iy - 2) <= (unsigned)(G - 5)) {
        // interior: all 21 taps in bounds, addresses = base + immediate
        const float* p = img + ix * S0 + iy * S1 + threadIdx.x;
#pragma unroll
        for (int o0 = -2; o0 <= 2; ++o0) {
#pragma unroll
            for (int o1 = -2; o1 <= 2; ++o1) {
                if (o0 * o0 + o1 * o1 == 8) continue;      // corners: never pass
                const float d2 = xs[o0 + 2] + ys[o1 + 2];
                const bool always = (o0 * o0 + o1 * o1 <= 1); // cross: always pass
                if (always || d2 < KW2) {
                    const float w = fmaxf(0.0f, fmaf(-sqrtf(d2), INV_KW, 1.0f));
                    acc = fmaf(w, __ldg(p + (o0 * S0 + o1 * S1)), acc);
                }
            }
        }
    } else {
        // rare edge threads: per-tap bounds
#pragma unroll
        for (int o0 = -2; o0 <= 2; ++o0) {
#pragma unroll
            for (int o1 = -2; o1 <= 2; ++o1) {
                if (o0 * o0 + o1 * o1 == 8) continue;
                const int jx = ix + o0;
                const int jy = iy + o1;
                const float d2 = xs[o0 + 2] + ys[o1 + 2];
                if (d2 < KW2 && (unsigned)jx < (unsigned)G && (unsigned)jy < (unsigned)G) {
                    const float w = fmaxf(0.0f, fmaf(-sqrtf(d2), INV_KW, 1.0f));
                    acc = fmaf(w, __ldg(img + jx * S0 + jy * S1 + threadIdx.x), acc);
                }
            }
        }
    }

    // block reduction (128 threads / 4 warps)
#pragma unroll
    for (int sft = 16; sft > 0; sft >>= 1)
        acc += __shfl_down_sync(0xFFFFFFFFu, acc, sft);
    __shared__ float wsum[4];
    const int lane = threadIdx.x & 31;
    const int wid  = threadIdx.x >> 5;
    if (lane == 0) wsum[wid] = acc;
    __syncthreads();
    if (threadIdx.x == 0)
        out[lor] = (wsum[0] + wsum[1] + wsum[2] + wsum[3]) * __ldg(&g_stp[set][lor]);
}

// ------------------------ generic fallback (R2 path, passed) ----------------
template <int P0, int P1, int P2, bool TPOSE>
__global__ __launch_bounds__(128)
void tor_generic_kernel(const float* __restrict__ img_in,
                        const int*   __restrict__ grid,
                        const float* __restrict__ center,
                        const float* __restrict__ size,
                        const float* __restrict__ lors,
                        float*       __restrict__ out,
                        int n_lors)
{
    const int lor = blockIdx.x;
    if (lor >= n_lors) return;
    const int g0 = grid[0], g1 = grid[1], g2 = grid[2];
    const int gs[3]   = { g0, g1, g2 };
    const int istr[3] = { g1 * g2, g2, 1 };
    const int n0 = gs[P0], n1 = gs[P1], n2 = gs[P2];
    int s0, s1, s2;
    const float* img;
    if (TPOSE) { s0 = G; s1 = GSQ; s2 = 1; img = g_imgT; }
    else       { s0 = istr[P0]; s1 = istr[P1]; s2 = istr[P2]; img = img_in; }

    const float sz0 = size[P0], sz1 = size[P1], sz2 = size[P2];
    const float vs0 = sz0 / (float)n0, vs1 = sz1 / (float)n1, vs2 = sz2 / (float)n2;
    const float lo0 = center[P0] - sz0 * 0.5f;
    const float lo1 = center[P1] - sz1 * 0.5f;
    const float lo2 = center[P2] - sz2 * 0.5f;

    const float* L = lors + (size_t)lor * 6;
    const float p1x = __ldg(L + 0), p1y = __ldg(L + 1), p1z = __ldg(L + 2);
    const float dx = __ldg(L + 3) - p1x, dy = __ldg(L + 4) - p1y, dz = __ldg(L + 5) - p1z;
    const float len = sqrtf(dx * dx + dy * dy + dz * dz);
    const float step = vs2 * len / fabsf(dz);
    const float inv_dz = 1.0f / dz, inv_vs0 = 1.0f / vs0, inv_vs1 = 1.0f / vs1;
    const float KW2 = 2.8647889756541160f, INV_KW = 0.59081795026046127f;

    float acc = 0.0f;
    for (int kz = threadIdx.x; kz < n2; kz += blockDim.x) {
        const float zc = lo2 + ((float)kz + 0.5f) * vs2;
        const float t  = (zc - p1z) * inv_dz;
        const float fx = (fmaf(t, dx, p1x) - lo0) * inv_vs0 - 0.5f;
        const float fy = (fmaf(t, dy, p1y) - lo1) * inv_vs1 - 0.5f;
        const int ix = __float2int_rn(fx);
        const int iy = __float2int_rn(fy);
#pragma unroll
        for (int o0 = -2; o0 <= 2; ++o0) {
#pragma unroll
            for (int o1 = -2; o1 <= 2; ++o1) {
                if (o0 * o0 + o1 * o1 == 8) continue;
                const int jx = ix + o0, jy = iy + o1;
                const float ddx = (float)jx - fx, ddy = (float)jy - fy;
                const float d2 = ddx * ddx + ddy * ddy;
                if (d2 < KW2 && (unsigned)jx < (unsigned)n0 && (unsigned)jy < (unsigned)n1) {
                    const float w = fmaxf(0.0f, fmaf(-sqrtf(d2), INV_KW, 1.0f));
                    acc = fmaf(w, __ldg(&img[jx * s0 + jy * s1 + kz * s2]), acc);
                }
            }
        }
    }
#pragma unroll
    for (int sft = 16; sft > 0; sft >>= 1)
        acc += __shfl_down_sync(0xFFFFFFFFu, acc, sft);
    __shared__ float wsum[4];
    if ((threadIdx.x & 31) == 0) wsum[threadIdx.x >> 5] = acc;
    __syncthreads();
    if (threadIdx.x == 0)
        out[lor] = (wsum[0] + wsum[1] + wsum[2] + wsum[3]) * step;
}

extern "C" void kernel_launch(void* const* d_in, const int* in_sizes, int n_in,
                              void* d_out, int out_size)
{
    const float* image  = (const float*)d_in[0];
    const int*   grid   = (const int*)  d_in[1];
    const float* center = (const float*)d_in[2];
    const float* size   = (const float*)d_in[3];
    const float* xlors  = (const float*)d_in[4];
    const float* ylors  = (const float*)d_in[5];
    const float* zlors  = (const float*)d_in[6];
    float* out = (float*)d_out;

    const int nx = in_sizes[4] / 6;
    const int ny = in_sizes[5] / 6;
    const int nz = in_sizes[6] / 6;

    const long long nimg = in_sizes[0];
    const bool fast = (nimg == (long long)G * G * G) &&
                      nx <= MAX_LORS && ny <= MAX_LORS && nz <= MAX_LORS;

    if (fast) {
        // transpose for px frame (walked image axis must be stride-1)
        {
            dim3 tb(32, 8), tg(G / 32, G / 32, G);
            transpose_bc_kernel<<<tg, tb>>>(image);
        }
        const int PT = 256;
        if (nx > 0) prep_kernel<2, 0, 1><<<(nx + PT - 1) / PT, PT>>>(grid, center, size, xlors, nx, 0);
        if (ny > 0) prep_kernel<1, 0, 2><<<(ny + PT - 1) / PT, PT>>>(grid, center, size, ylors, ny, 1);
        if (nz > 0) prep_kernel<0, 1, 2><<<(nz + PT - 1) / PT, PT>>>(grid, center, size, zlors, nz, 2);

        // px: imgx[jx][jy][kz] = image[jy][kz][jx] = g_imgT[jy][jx][kz] -> S0=G, S1=GSQ (TPOSE)
        if (nx > 0) tor_fast_kernel<G,   GSQ, true ><<<nx, G>>>(image, 0, out);
        // py: imgy[jx][jy][kz] = image[jy][jx][kz] -> S0=G, S1=GSQ
        if (ny > 0) tor_fast_kernel<G,   GSQ, false><<<ny, G>>>(image, 1, out + nx);
        // pz: image[jx][jy][kz] -> S0=GSQ, S1=G
        if (nz > 0) tor_fast_kernel<GSQ, G,   false><<<nz, G>>>(image, 2, out + nx + ny);
    } else {
        if (nx > 0) tor_generic_kernel<2, 0, 1, false><<<nx, 128>>>(image, grid, center, size, xlors, out, nx);
        if (ny > 0) tor_generic_kernel<1, 0, 2, false><<<ny, 128>>>(image, grid, center, size, ylors, out + nx, ny);
        if (nz > 0) tor_generic_kernel<0, 1, 2, false><<<nz, 128>>>(image, grid, center, size, zlors, out + nx + ny, nz);
    }
}